// round 1
// baseline (speedup 1.0000x reference)
#include <cuda_runtime.h>
#include <math.h>

// Problem constants (fixed shapes from reference setup_inputs)
#define B_    16
#define C_    1024
#define T_    64
#define N_    12
#define BT_   (B_ * T_)       // 1024 frames
#define NF_   1024            // NFR = NFG = NFG_ONE
#define ROWS_ (BT_ * N_)      // 12288
#define TN_   (T_ * N_)       // 768

// Scratch (static device globals — allocation-free per harness rules)
__device__ float g_feat[ROWS_ * NF_];   // [12288, 1024] feat
__device__ float g_tM[ROWS_ * NF_];     // feat @ Mw
__device__ float g_G[ROWS_ * NF_];      // feat @ w_gcn
__device__ float g_Mw[NF_ * NF_];       // Wtheta @ Wphi^T
__device__ float g_vtp[NF_];            // Wtheta @ b_phi
__device__ float g_vpt[NF_];            // Wphi   @ b_theta
__device__ float g_bb[1];               // b_theta . b_phi

// ---------------------------------------------------------------------------
// Transpose: x[B,C,T,N] -> feat[(b*T+t)*N+n, c]  (per-b transpose of 1024x768)
// ---------------------------------------------------------------------------
__global__ void transpose_x(const float* __restrict__ x) {
    __shared__ float tile[32][33];
    const int b   = blockIdx.z;
    const int c0  = blockIdx.y * 32;
    const int tn0 = blockIdx.x * 32;
    const int tx = threadIdx.x, ty = threadIdx.y;  // 32 x 8

    const float* xp = x + ((size_t)b * C_ + c0) * TN_ + tn0;
#pragma unroll
    for (int i = 0; i < 32; i += 8)
        tile[ty + i][tx] = xp[(size_t)(ty + i) * TN_ + tx];
    __syncthreads();
    float* fp = g_feat + ((size_t)b * TN_ + tn0) * NF_ + c0;
#pragma unroll
    for (int i = 0; i < 32; i += 8)
        fp[(size_t)(ty + i) * NF_ + tx] = tile[tx][ty + i];
}

// ---------------------------------------------------------------------------
// Bias cross-term vectors: vtp[c] = sum_r Wt[c,r]*bp[r], vpt[c] = sum_r Wp[c,r]*bt[r]
// ---------------------------------------------------------------------------
__global__ void bias_vecs(const float* __restrict__ wt, const float* __restrict__ bt,
                          const float* __restrict__ wp, const float* __restrict__ bp) {
    const int c = blockIdx.x * blockDim.x + threadIdx.x;
    if (c < NF_) {
        float a = 0.f, b2 = 0.f;
        const float* wtr = wt + (size_t)c * NF_;
        const float* wpr = wp + (size_t)c * NF_;
        for (int r = 0; r < NF_; ++r) {
            a  += wtr[r] * bp[r];
            b2 += wpr[r] * bt[r];
        }
        g_vtp[c] = a;
        g_vpt[c] = b2;
    }
    if (blockIdx.x == 0 && threadIdx.x == 0) {
        float s = 0.f;
        for (int r = 0; r < NF_; ++r) s += bt[r] * bp[r];
        g_bb[0] = s;
    }
}

// ---------------------------------------------------------------------------
// Tiled SGEMM: C[M,N] = A[M,K] * op(B). TRANSB=0: B is [K,N] row-major.
// TRANSB=1: B is [N,K] row-major (C = A * B^T). 128x128 tile, K-step 8,
// 256 threads, 8x8 accumulators per thread. M,N mult of 128; K mult of 8.
// ---------------------------------------------------------------------------
template <int TRANSB>
__global__ void __launch_bounds__(256) sgemm128(const float* __restrict__ A,
                                                const float* __restrict__ B,
                                                float* __restrict__ C,
                                                int M, int N, int K) {
    __shared__ float As[8][128];
    __shared__ float Bs[8][128];
    const int tid = threadIdx.x;
    const int bx = blockIdx.x, by = blockIdx.y;
    const int tx = tid & 15, ty = tid >> 4;

    const int arow = tid >> 1;
    const int ac4  = (tid & 1) << 2;
    const float* Ap = A + (size_t)(by * 128 + arow) * K + ac4;

    const float* Bp;
    int brow = 0, bc = 0;
    if (TRANSB) {
        Bp = B + (size_t)(bx * 128 + arow) * K + ac4;
    } else {
        brow = tid >> 5;
        bc   = (tid & 31) << 2;
        Bp   = B + (size_t)brow * N + bx * 128 + bc;
    }

    float acc[8][8];
#pragma unroll
    for (int i = 0; i < 8; i++)
#pragma unroll
        for (int j = 0; j < 8; j++) acc[i][j] = 0.f;

    for (int k0 = 0; k0 < K; k0 += 8) {
        float4 av = *(const float4*)(Ap + k0);
        As[ac4 + 0][arow] = av.x; As[ac4 + 1][arow] = av.y;
        As[ac4 + 2][arow] = av.z; As[ac4 + 3][arow] = av.w;
        if (TRANSB) {
            float4 bv = *(const float4*)(Bp + k0);
            Bs[ac4 + 0][arow] = bv.x; Bs[ac4 + 1][arow] = bv.y;
            Bs[ac4 + 2][arow] = bv.z; Bs[ac4 + 3][arow] = bv.w;
        } else {
            float4 bv = *(const float4*)(Bp + (size_t)k0 * N);
            *(float4*)&Bs[brow][bc] = bv;
        }
        __syncthreads();
#pragma unroll
        for (int k = 0; k < 8; ++k) {
            float a[8], b[8];
            *(float4*)&a[0] = *(const float4*)&As[k][ty * 8];
            *(float4*)&a[4] = *(const float4*)&As[k][ty * 8 + 4];
            *(float4*)&b[0] = *(const float4*)&Bs[k][tx * 8];
            *(float4*)&b[4] = *(const float4*)&Bs[k][tx * 8 + 4];
#pragma unroll
            for (int i = 0; i < 8; i++)
#pragma unroll
                for (int j = 0; j < 8; j++) acc[i][j] += a[i] * b[j];
        }
        __syncthreads();
    }
    float* Cp = C + (size_t)(by * 128 + ty * 8) * N + bx * 128 + tx * 8;
#pragma unroll
    for (int i = 0; i < 8; i++) {
        *(float4*)(Cp + (size_t)i * N)     = make_float4(acc[i][0], acc[i][1], acc[i][2], acc[i][3]);
        *(float4*)(Cp + (size_t)i * N + 4) = make_float4(acc[i][4], acc[i][5], acc[i][6], acc[i][7]);
    }
}

// ---------------------------------------------------------------------------
// Block sum over 512 threads
// ---------------------------------------------------------------------------
__device__ __forceinline__ float blockSum512(float v, float* red) {
    const int lane = threadIdx.x & 31, warp = threadIdx.x >> 5;
#pragma unroll
    for (int o = 16; o > 0; o >>= 1) v += __shfl_xor_sync(0xffffffffu, v, o);
    if (lane == 0) red[warp] = v;
    __syncthreads();
    if (threadIdx.x == 0) {
        float s = 0.f;
        for (int i = 0; i < 16; i++) s += red[i];
        red[16] = s;
    }
    __syncthreads();
    float r = red[16];
    __syncthreads();
    return r;
}

// ---------------------------------------------------------------------------
// Per-frame: logits (via tM@feat^T + bias terms), mask, softmax,
// agg = rg @ G_f, LayerNorm over [12,1024], ReLU.  One block per frame.
// ---------------------------------------------------------------------------
__global__ void __launch_bounds__(512) frame_kernel(const float* __restrict__ Abox,
                                                    const float* __restrict__ ln_w,
                                                    const float* __restrict__ ln_b,
                                                    float* __restrict__ out,
                                                    float* __restrict__ rg_out) {
    const int f = blockIdx.x;
    const int tid = threadIdx.x;
    const int lane = tid & 31, warp = tid >> 5;

    __shared__ float px[12], py[12], sqs[12];
    __shared__ float s_u[12], s_v[12];
    __shared__ float s_rg[12][12];
    __shared__ float red[17];

    if (tid < 12) {
        const float* bx = Abox + ((size_t)f * 12 + tid) * 4;
        float cx = (bx[0] + bx[2]) * 0.5f;
        float cy = (bx[1] + bx[3]) * 0.5f;
        px[tid] = cx; py[tid] = cy; sqs[tid] = cx * cx + cy * cy;
    }

    // phase 1: bias cross terms u_n = feat_n . vtp, v_n = feat_n . vpt
    if (warp < 12) {
        const float* frow = g_feat + ((size_t)f * 12 + warp) * NF_;
        float ua = 0.f, va = 0.f;
#pragma unroll
        for (int k = 0; k < 32; k++) {
            float fv = frow[lane + 32 * k];
            ua += fv * g_vtp[lane + 32 * k];
            va += fv * g_vpt[lane + 32 * k];
        }
#pragma unroll
        for (int o = 16; o > 0; o >>= 1) {
            ua += __shfl_xor_sync(0xffffffffu, ua, o);
            va += __shfl_xor_sync(0xffffffffu, va, o);
        }
        if (lane == 0) { s_u[warp] = ua; s_v[warp] = va; }
    }
    __syncthreads();

    // phase 2: logits row n = warp n; mask + softmax
    if (warp < 12) {
        const int n = warp;
        const float* tMrow = g_tM + ((size_t)f * 12 + n) * NF_;
        float tr[32];
#pragma unroll
        for (int k = 0; k < 32; k++) tr[k] = tMrow[lane + 32 * k];
        float lg[12];
#pragma unroll
        for (int m = 0; m < 12; m++) {
            const float* fm = g_feat + ((size_t)f * 12 + m) * NF_;
            float a = 0.f;
#pragma unroll
            for (int k = 0; k < 32; k++) a += tr[k] * fm[lane + 32 * k];
#pragma unroll
            for (int o = 16; o > 0; o >>= 1) a += __shfl_xor_sync(0xffffffffu, a, o);
            lg[m] = a;
        }
        if (lane == 0) {
            const float bb = g_bb[0];
            const float scale = 0.03125f;  // 1/sqrt(1024)
            float e[12];
            bool msk[12];
            float mx = -INFINITY;
#pragma unroll
            for (int m = 0; m < 12; m++) {
                // replicate reference distance arithmetic
                float d2 = sqs[n] - 2.f * (px[n] * px[m] + py[n] * py[m]) + sqs[m];
                d2 = fmaxf(d2, 0.f);
                float dist = sqrtf(d2);
                msk[m] = (dist > 0.4f);  // POS_THRESHOLD * OW
                float v = (lg[m] + s_u[n] + s_v[m] + bb) * scale;
                e[m] = v;
                if (!msk[m]) mx = fmaxf(mx, v);
            }
            float se = 0.f;
#pragma unroll
            for (int m = 0; m < 12; m++) {
                float ev = msk[m] ? 0.f : expf(e[m] - mx);
                e[m] = ev;
                se += ev;
            }
            float inv = 1.f / se;
#pragma unroll
            for (int m = 0; m < 12; m++) {
                float r = e[m] * inv;
                s_rg[n][m] = r;
                if (rg_out) rg_out[((size_t)f * 12 + n) * 12 + m] = r;
            }
        }
    }
    __syncthreads();

    // phase 3: agg = rg @ G_f, kept in registers; then LayerNorm + ReLU
    float aggv[2][12];
#pragma unroll
    for (int cc = 0; cc < 2; cc++) {
        const int c = tid + cc * 512;
        float g[12];
#pragma unroll
        for (int m = 0; m < 12; m++) g[m] = g_G[((size_t)f * 12 + m) * NF_ + c];
#pragma unroll
        for (int n = 0; n < 12; n++) {
            float a = 0.f;
#pragma unroll
            for (int m = 0; m < 12; m++) a += s_rg[n][m] * g[m];
            aggv[cc][n] = a;
        }
    }
    float lsum = 0.f;
#pragma unroll
    for (int cc = 0; cc < 2; cc++)
#pragma unroll
        for (int n = 0; n < 12; n++) lsum += aggv[cc][n];
    const float mu = blockSum512(lsum, red) * (1.f / 12288.f);

    float lsq = 0.f;
#pragma unroll
    for (int cc = 0; cc < 2; cc++)
#pragma unroll
        for (int n = 0; n < 12; n++) {
            float d = aggv[cc][n] - mu;
            lsq += d * d;
        }
    const float var = blockSum512(lsq, red) * (1.f / 12288.f);
    const float rstd = rsqrtf(var + 1e-5f);

#pragma unroll
    for (int cc = 0; cc < 2; cc++) {
        const int c = tid + cc * 512;
#pragma unroll
        for (int n = 0; n < 12; n++) {
            float y = (aggv[cc][n] - mu) * rstd * ln_w[n * NF_ + c] + ln_b[n * NF_ + c];
            out[((size_t)f * 12 + n) * NF_ + c] = fmaxf(y, 0.f);
        }
    }
}

// ---------------------------------------------------------------------------
extern "C" void kernel_launch(void* const* d_in, const int* in_sizes, int n_in,
                              void* d_out, int out_size) {
    const float* x  = (const float*)d_in[0];
    const float* A  = (const float*)d_in[1];
    const float* wt = (const float*)d_in[2];
    const float* bt = (const float*)d_in[3];
    const float* wp = (const float*)d_in[4];
    const float* bp = (const float*)d_in[5];
    const float* wg = (const float*)d_in[6];
    const float* lw = (const float*)d_in[7];
    const float* lb = (const float*)d_in[8];

    float* out = (float*)d_out;
    // tuple output: [out (12288*1024), relation_graph (1024*144)]
    float* rg = (out_size >= (int)(ROWS_ * NF_ + BT_ * N_ * N_))
                    ? out + (size_t)ROWS_ * NF_
                    : nullptr;

    float *feat, *tM, *G, *Mw;
    cudaGetSymbolAddress((void**)&feat, g_feat);
    cudaGetSymbolAddress((void**)&tM, g_tM);
    cudaGetSymbolAddress((void**)&G, g_G);
    cudaGetSymbolAddress((void**)&Mw, g_Mw);

    // 1. x -> feat
    transpose_x<<<dim3(TN_ / 32, C_ / 32, B_), dim3(32, 8)>>>(x);
    // 2. Mw = Wtheta @ Wphi^T  (NT)
    sgemm128<1><<<dim3(NF_ / 128, NF_ / 128), 256>>>(wt, wp, Mw, NF_, NF_, NF_);
    // 3. bias cross vectors
    bias_vecs<<<NF_ / 128, 128>>>(wt, bt, wp, bp);
    // 4. tM = feat @ Mw  (NN)
    sgemm128<0><<<dim3(NF_ / 128, ROWS_ / 128), 256>>>(feat, Mw, tM, ROWS_, NF_, NF_);
    // 5. G = feat @ w_gcn  (NN)
    sgemm128<0><<<dim3(NF_ / 128, ROWS_ / 128), 256>>>(feat, wg, G, ROWS_, NF_, NF_);
    // 6. per-frame logits/softmax/agg/LN/ReLU
    frame_kernel<<<BT_, 512>>>(A, lw, lb, out, rg);
}

// round 4
// speedup vs baseline: 2.7693x; 2.7693x over previous
#include <cuda_runtime.h>
#include <math.h>
#include <stdint.h>

// Problem constants
#define B_    16
#define C_    1024
#define T_    64
#define N_    12
#define BT_   (B_ * T_)       // 1024 frames
#define NF_   1024
#define ROWS_ (BT_ * N_)      // 12288
#define TN_   (T_ * N_)       // 768
#define NB_   2048            // fused B rows: [MwT | wg^T]

// Scratch (static device globals)
__device__ float g_feat[ROWS_ * NF_];   // feat, RNA-rounded to tf32
__device__ float g_TG[ROWS_ * NB_];     // [tM | G] fused output
__device__ float g_BigB[NB_ * NF_];     // rows 0-1023: MwT, rows 1024-2047: wg^T
__device__ float g_wtr[NF_ * NF_];      // Wtheta rounded
__device__ float g_wpr[NF_ * NF_];      // Wphi rounded
__device__ float g_vtp[NF_];
__device__ float g_vpt[NF_];
__device__ float g_bb[1];

// ---------------------------------------------------------------------------
// Helpers (baseline PTX only — no arch-'a' gated instructions)
// ---------------------------------------------------------------------------
__device__ __forceinline__ float rna_tf32(float x) {
    float r;
    asm("cvt.rna.tf32.f32 %0, %1;" : "=f"(r) : "f"(x));
    return r;
}
__device__ __forceinline__ uint32_t smem_u32(const void* p) {
    uint32_t a;
    asm("{ .reg .u64 t; cvta.to.shared.u64 t, %1; cvt.u32.u64 %0, t; }" : "=r"(a) : "l"(p));
    return a;
}
__device__ __forceinline__ void cp16(uint32_t s, const void* g) {
    asm volatile("cp.async.cg.shared.global [%0], [%1], 16;" :: "r"(s), "l"(g) : "memory");
}
#define CP_COMMIT() asm volatile("cp.async.commit_group;" ::: "memory")
#define SWZ(x) ((x) ^ (((x) >> 3) & 0x70))

__device__ __forceinline__ void ldsm4(uint32_t* r, uint32_t addr) {
    asm volatile("ldmatrix.sync.aligned.m8n8.x4.shared.b16 {%0,%1,%2,%3}, [%4];"
                 : "=r"(r[0]), "=r"(r[1]), "=r"(r[2]), "=r"(r[3]) : "r"(addr));
}
__device__ __forceinline__ void mma_tf32(float* c, const uint32_t* a, uint32_t b0, uint32_t b1) {
    asm volatile("mma.sync.aligned.m16n8k8.row.col.f32.tf32.tf32.f32 "
                 "{%0,%1,%2,%3}, {%4,%5,%6,%7}, {%8,%9}, {%0,%1,%2,%3};"
                 : "+f"(c[0]), "+f"(c[1]), "+f"(c[2]), "+f"(c[3])
                 : "r"(a[0]), "r"(a[1]), "r"(a[2]), "r"(a[3]), "r"(b0), "r"(b1));
}

// ---------------------------------------------------------------------------
// Tensor-core tf32 GEMM: C[m,n] = sum_k A[m,k]*Bm[n,k]; A[M,K], Bm[N,K] row-major.
// Block 128x128, K-chunk 32, 3-stage cp.async, 8 warps (each 64x32).
// ---------------------------------------------------------------------------
#define BM 128
#define BN 128
#define BK 32
#define STAGES 3
#define STAGE_BYTES 16384
#define GEMM_SMEM (STAGES * 2 * STAGE_BYTES)  // 98304

template <bool ROUND>
__global__ void __launch_bounds__(256, 1) mma_gemm(const float* __restrict__ A,
                                                   const float* __restrict__ Bm,
                                                   float* __restrict__ C,
                                                   int K, int ldc) {
    extern __shared__ char smem[];
    const uint32_t sb = smem_u32(smem);
    const int tid = threadIdx.x, lane = tid & 31, wid = tid >> 5;
    const int m0 = blockIdx.y * BM, n0 = blockIdx.x * BN;
    const int warp_m = wid & 1, warp_n = wid >> 1;

    // cp.async tiling: 8 threads x 16B per 128B row, 32 rows per pass
    const int r = tid >> 3;
    const int o16 = (tid & 7) << 4;
    const int c4 = (tid & 7) << 2;

    float acc[4][4][4];
#pragma unroll
    for (int i = 0; i < 4; i++)
#pragma unroll
        for (int j = 0; j < 4; j++)
#pragma unroll
            for (int k = 0; k < 4; k++) acc[i][j][k] = 0.f;

    // ldmatrix per-lane UNSWIZZLED base offsets (swizzle applied per k-step;
    // base has bits 5-6 clear so base + ks*32 never carries pre-swizzle)
    const int lrow = lane & 15;
    const int lcol = (lane >> 4) << 4;
    uint32_t a_base[4], b_base[2];
#pragma unroll
    for (int mt = 0; mt < 4; mt++)
        a_base[mt] = (uint32_t)((warp_m * 64 + mt * 16 + lrow) * 128 + lcol);
#pragma unroll
    for (int nh = 0; nh < 2; nh++)
        b_base[nh] = (uint32_t)((warp_n * 32 + nh * 16 + lrow) * 128 + lcol);

#define LOAD_STAGE(chunk, stage)                                                   \
    do {                                                                           \
        uint32_t sA = sb + (stage) * STAGE_BYTES;                                  \
        uint32_t sB = sb + STAGES * STAGE_BYTES + (stage) * STAGE_BYTES;           \
        int k0 = (chunk) * BK;                                                     \
        _Pragma("unroll") for (int t = 0; t < 4; t++) {                            \
            int rr = r + t * 32;                                                   \
            cp16(sA + SWZ((uint32_t)(rr * 128 + o16)),                             \
                 A + (size_t)(m0 + rr) * K + k0 + c4);                             \
        }                                                                          \
        _Pragma("unroll") for (int t = 0; t < 4; t++) {                            \
            int rr = r + t * 32;                                                   \
            cp16(sB + SWZ((uint32_t)(rr * 128 + o16)),                             \
                 Bm + (size_t)(n0 + rr) * K + k0 + c4);                            \
        }                                                                          \
        CP_COMMIT();                                                               \
    } while (0)

    LOAD_STAGE(0, 0);
    LOAD_STAGE(1, 1);

    const int nk = K / BK;
    for (int i = 0; i < nk; i++) {
        const int st = i % STAGES;
        if (i + 2 < nk) {
            asm volatile("cp.async.wait_group 1;" ::: "memory");
            __syncthreads();
            LOAD_STAGE(i + 2, (i + 2) % STAGES);
        } else {
            asm volatile("cp.async.wait_group 0;" ::: "memory");
            __syncthreads();
        }
        const uint32_t sA = sb + st * STAGE_BYTES;
        const uint32_t sB = sb + STAGES * STAGE_BYTES + st * STAGE_BYTES;
#pragma unroll
        for (int ks = 0; ks < 4; ks++) {
            uint32_t a[4][4], b[2][4];
#pragma unroll
            for (int mt = 0; mt < 4; mt++)
                ldsm4(a[mt], sA + SWZ(a_base[mt] + (uint32_t)(ks * 32)));
#pragma unroll
            for (int nh = 0; nh < 2; nh++)
                ldsm4(b[nh], sB + SWZ(b_base[nh] + (uint32_t)(ks * 32)));
#pragma unroll
            for (int mt = 0; mt < 4; mt++)
#pragma unroll
                for (int nt = 0; nt < 4; nt++)
                    mma_tf32(acc[mt][nt], a[mt], b[nt >> 1][nt & 1], b[nt >> 1][(nt & 1) + 2]);
        }
    }
#undef LOAD_STAGE

    // Epilogue: direct float2 stores
    const int mrow = lane >> 2;
    const int mcol = (lane & 3) << 1;
#pragma unroll
    for (int mt = 0; mt < 4; mt++) {
#pragma unroll
        for (int nt = 0; nt < 4; nt++) {
            int row = m0 + warp_m * 64 + mt * 16 + mrow;
            int col = n0 + warp_n * 32 + nt * 8 + mcol;
            float2 v0 = make_float2(acc[mt][nt][0], acc[mt][nt][1]);
            float2 v1 = make_float2(acc[mt][nt][2], acc[mt][nt][3]);
            if (ROUND) {
                v0.x = rna_tf32(v0.x); v0.y = rna_tf32(v0.y);
                v1.x = rna_tf32(v1.x); v1.y = rna_tf32(v1.y);
            }
            *(float2*)&C[(size_t)row * ldc + col] = v0;
            *(float2*)&C[(size_t)(row + 8) * ldc + col] = v1;
        }
    }
}

// ---------------------------------------------------------------------------
// Transpose x[B,C,T,N] -> feat[(b*T+t)*N+n, c], RNA-rounded to tf32
// ---------------------------------------------------------------------------
__global__ void transpose_x(const float* __restrict__ x) {
    __shared__ float tile[32][33];
    const int b = blockIdx.z;
    const int c0 = blockIdx.y * 32;
    const int tn0 = blockIdx.x * 32;
    const int tx = threadIdx.x, ty = threadIdx.y;
    const float* xp = x + ((size_t)b * C_ + c0) * TN_ + tn0;
#pragma unroll
    for (int i = 0; i < 32; i += 8)
        tile[ty + i][tx] = xp[(size_t)(ty + i) * TN_ + tx];
    __syncthreads();
    float* fp = g_feat + ((size_t)b * TN_ + tn0) * NF_ + c0;
#pragma unroll
    for (int i = 0; i < 32; i += 8)
        fp[(size_t)(ty + i) * NF_ + tx] = rna_tf32(tile[tx][ty + i]);
}

// w_gcn [K,N] -> g_BigB rows 1024..2047 ([N,K]), rounded
__global__ void transpose_wg(const float* __restrict__ w) {
    __shared__ float tile[32][33];
    const int k0 = blockIdx.y * 32;
    const int n0 = blockIdx.x * 32;
    const int tx = threadIdx.x, ty = threadIdx.y;
#pragma unroll
    for (int i = 0; i < 32; i += 8)
        tile[ty + i][tx] = w[(size_t)(k0 + ty + i) * NF_ + n0 + tx];
    __syncthreads();
    float* dst = g_BigB + (size_t)NF_ * NF_;
#pragma unroll
    for (int i = 0; i < 32; i += 8)
        dst[(size_t)(n0 + ty + i) * NF_ + k0 + tx] = rna_tf32(tile[tx][ty + i]);
}

__global__ void round_copy(const float4* __restrict__ in, float4* __restrict__ out) {
    const int i = blockIdx.x * blockDim.x + threadIdx.x;
    float4 v = in[i];
    v.x = rna_tf32(v.x); v.y = rna_tf32(v.y);
    v.z = rna_tf32(v.z); v.w = rna_tf32(v.w);
    out[i] = v;
}

// ---------------------------------------------------------------------------
// Bias cross-term vectors (exact fp32)
// ---------------------------------------------------------------------------
__global__ void bias_vecs(const float* __restrict__ wt, const float* __restrict__ bt,
                          const float* __restrict__ wp, const float* __restrict__ bp) {
    const int c = blockIdx.x * blockDim.x + threadIdx.x;
    if (c < NF_) {
        float a = 0.f, b2 = 0.f;
        const float* wtr = wt + (size_t)c * NF_;
        const float* wpr = wp + (size_t)c * NF_;
        for (int r = 0; r < NF_; ++r) {
            a += wtr[r] * bp[r];
            b2 += wpr[r] * bt[r];
        }
        g_vtp[c] = a;
        g_vpt[c] = b2;
    }
    if (blockIdx.x == 0 && threadIdx.x == 0) {
        float s = 0.f;
        for (int r = 0; r < NF_; ++r) s += bt[r] * bp[r];
        g_bb[0] = s;
    }
}

// ---------------------------------------------------------------------------
__device__ __forceinline__ float blockSum512(float v, float* red) {
    const int lane = threadIdx.x & 31, warp = threadIdx.x >> 5;
#pragma unroll
    for (int o = 16; o > 0; o >>= 1) v += __shfl_xor_sync(0xffffffffu, v, o);
    if (lane == 0) red[warp] = v;
    __syncthreads();
    if (threadIdx.x == 0) {
        float s = 0.f;
        for (int i = 0; i < 16; i++) s += red[i];
        red[16] = s;
    }
    __syncthreads();
    float r = red[16];
    __syncthreads();
    return r;
}

__global__ void __launch_bounds__(512) frame_kernel(const float* __restrict__ Abox,
                                                    const float* __restrict__ ln_w,
                                                    const float* __restrict__ ln_b,
                                                    float* __restrict__ out,
                                                    float* __restrict__ rg_out) {
    const int f = blockIdx.x;
    const int tid = threadIdx.x;
    const int lane = tid & 31, warp = tid >> 5;

    __shared__ float px[12], py[12], sqs[12];
    __shared__ float s_u[12], s_v[12];
    __shared__ float s_rg[12][12];
    __shared__ float red[17];

    if (tid < 12) {
        const float* bx = Abox + ((size_t)f * 12 + tid) * 4;
        float cx = (bx[0] + bx[2]) * 0.5f;
        float cy = (bx[1] + bx[3]) * 0.5f;
        px[tid] = cx; py[tid] = cy; sqs[tid] = cx * cx + cy * cy;
    }

    if (warp < 12) {
        const float* frow = g_feat + ((size_t)f * 12 + warp) * NF_;
        float ua = 0.f, va = 0.f;
#pragma unroll
        for (int k = 0; k < 32; k++) {
            float fv = frow[lane + 32 * k];
            ua += fv * g_vtp[lane + 32 * k];
            va += fv * g_vpt[lane + 32 * k];
        }
#pragma unroll
        for (int o = 16; o > 0; o >>= 1) {
            ua += __shfl_xor_sync(0xffffffffu, ua, o);
            va += __shfl_xor_sync(0xffffffffu, va, o);
        }
        if (lane == 0) { s_u[warp] = ua; s_v[warp] = va; }
    }
    __syncthreads();

    if (warp < 12) {
        const int n = warp;
        const float* tMrow = g_TG + ((size_t)f * 12 + n) * NB_;
        float tr[32];
#pragma unroll
        for (int k = 0; k < 32; k++) tr[k] = tMrow[lane + 32 * k];
        float lg[12];
#pragma unroll
        for (int m = 0; m < 12; m++) {
            const float* fm = g_feat + ((size_t)f * 12 + m) * NF_;
            float a = 0.f;
#pragma unroll
            for (int k = 0; k < 32; k++) a += tr[k] * fm[lane + 32 * k];
#pragma unroll
            for (int o = 16; o > 0; o >>= 1) a += __shfl_xor_sync(0xffffffffu, a, o);
            lg[m] = a;
        }
        if (lane == 0) {
            const float bb = g_bb[0];
            const float scale = 0.03125f;
            float e[12];
            bool msk[12];
            float mx = -INFINITY;
#pragma unroll
            for (int m = 0; m < 12; m++) {
                float d2 = sqs[n] - 2.f * (px[n] * px[m] + py[n] * py[m]) + sqs[m];
                d2 = fmaxf(d2, 0.f);
                float dist = sqrtf(d2);
                msk[m] = (dist > 0.4f);
                float v = (lg[m] + s_u[n] + s_v[m] + bb) * scale;
                e[m] = v;
                if (!msk[m]) mx = fmaxf(mx, v);
            }
            float se = 0.f;
#pragma unroll
            for (int m = 0; m < 12; m++) {
                float ev = msk[m] ? 0.f : expf(e[m] - mx);
                e[m] = ev;
                se += ev;
            }
            float inv = 1.f / se;
#pragma unroll
            for (int m = 0; m < 12; m++) {
                float r = e[m] * inv;
                s_rg[n][m] = r;
                if (rg_out) rg_out[((size_t)f * 12 + n) * 12 + m] = r;
            }
        }
    }
    __syncthreads();

    float aggv[2][12];
#pragma unroll
    for (int cc = 0; cc < 2; cc++) {
        const int c = tid + cc * 512;
        float g[12];
#pragma unroll
        for (int m = 0; m < 12; m++)
            g[m] = g_TG[((size_t)f * 12 + m) * NB_ + NF_ + c];
#pragma unroll
        for (int n = 0; n < 12; n++) {
            float a = 0.f;
#pragma unroll
            for (int m = 0; m < 12; m++) a += s_rg[n][m] * g[m];
            aggv[cc][n] = a;
        }
    }
    float lsum = 0.f;
#pragma unroll
    for (int cc = 0; cc < 2; cc++)
#pragma unroll
        for (int n = 0; n < 12; n++) lsum += aggv[cc][n];
    const float mu = blockSum512(lsum, red) * (1.f / 12288.f);

    float lsq = 0.f;
#pragma unroll
    for (int cc = 0; cc < 2; cc++)
#pragma unroll
        for (int n = 0; n < 12; n++) {
            float d = aggv[cc][n] - mu;
            lsq += d * d;
        }
    const float var = blockSum512(lsq, red) * (1.f / 12288.f);
    const float rstd = rsqrtf(var + 1e-5f);

#pragma unroll
    for (int cc = 0; cc < 2; cc++) {
        const int c = tid + cc * 512;
#pragma unroll
        for (int n = 0; n < 12; n++) {
            float y = (aggv[cc][n] - mu) * rstd * ln_w[n * NF_ + c] + ln_b[n * NF_ + c];
            out[((size_t)f * 12 + n) * NF_ + c] = fmaxf(y, 0.f);
        }
    }
}

// ---------------------------------------------------------------------------
extern "C" void kernel_launch(void* const* d_in, const int* in_sizes, int n_in,
                              void* d_out, int out_size) {
    const float* x  = (const float*)d_in[0];
    const float* A  = (const float*)d_in[1];
    const float* wt = (const float*)d_in[2];
    const float* bt = (const float*)d_in[3];
    const float* wp = (const float*)d_in[4];
    const float* bp = (const float*)d_in[5];
    const float* wg = (const float*)d_in[6];
    const float* lw = (const float*)d_in[7];
    const float* lb = (const float*)d_in[8];

    float* out = (float*)d_out;
    float* rg = (out_size >= (int)(ROWS_ * NF_ + BT_ * N_ * N_))
                    ? out + (size_t)ROWS_ * NF_
                    : nullptr;

    float *feat, *TG, *BigB, *wtr, *wpr;
    cudaGetSymbolAddress((void**)&feat, g_feat);
    cudaGetSymbolAddress((void**)&TG, g_TG);
    cudaGetSymbolAddress((void**)&BigB, g_BigB);
    cudaGetSymbolAddress((void**)&wtr, g_wtr);
    cudaGetSymbolAddress((void**)&wpr, g_wpr);

    cudaFuncSetAttribute(mma_gemm<true>,
                         cudaFuncAttributeMaxDynamicSharedMemorySize, GEMM_SMEM);
    cudaFuncSetAttribute(mma_gemm<false>,
                         cudaFuncAttributeMaxDynamicSharedMemorySize, GEMM_SMEM);

    // Prep
    transpose_x<<<dim3(TN_ / 32, C_ / 32, B_), dim3(32, 8)>>>(x);
    round_copy<<<1024, 256>>>((const float4*)wt, (float4*)wtr);
    round_copy<<<1024, 256>>>((const float4*)wp, (float4*)wpr);
    transpose_wg<<<dim3(32, 32), dim3(32, 8)>>>(wg);
    bias_vecs<<<NF_ / 128, 128>>>(wt, bt, wp, bp);

    // MwT[n,k] = sum_r wphi[n,r]*wtheta[k,r]  -> BigB rows 0..1023 (rounded)
    mma_gemm<true><<<dim3(NF_ / BN, NF_ / BM), 256, GEMM_SMEM>>>(wpr, wtr, BigB, NF_, NF_);
    // [tM | G] = feat @ [MwT | wg^T]^T   (fused, N = 2048)
    mma_gemm<false><<<dim3(NB_ / BN, ROWS_ / BM), 256, GEMM_SMEM>>>(feat, BigB, TG, NF_, NB_);

    frame_kernel<<<BT_, 512>>>(A, lw, lb, out, rg);
}